// round 1
// baseline (speedup 1.0000x reference)
#include <cuda_runtime.h>
#include <math.h>

#define NB  4
#define SEQ 2048
#define DIM 1024

// Scratch (device globals — no allocations allowed in kernel_launch)
__device__ float g_wv[(size_t)NB*SEQ*DIM];   // 32 MB
__device__ float g_wq[(size_t)NB*SEQ*DIM];   // 32 MB
__device__ float g_wk[(size_t)NB*SEQ*DIM];   // 32 MB
__device__ float g_p [(size_t)NB*SEQ*SEQ];   // 64 MB  (scores, stored transposed: P[n][k][q])

#define BM 128
#define BN 128
#define BK 16

// C[m,n] = sum_k A[m*lda + k] * B[n*ldb + k]   (both operands K-contiguous, "NT")
__global__ __launch_bounds__(256) void gemm_nt(
    const float* __restrict__ A, const float* __restrict__ B, float* __restrict__ C,
    int K, int lda, int ldb, int ldc,
    size_t sA, size_t sB, size_t sC)
{
    A += (size_t)blockIdx.z * sA;
    B += (size_t)blockIdx.z * sB;
    C += (size_t)blockIdx.z * sC;

    __shared__ float As[BK][BM];
    __shared__ float Bs[BK][BN];

    const int bm  = blockIdx.y * BM;
    const int bn  = blockIdx.x * BN;
    const int tid = threadIdx.x;
    const int tx  = tid & 15;
    const int ty  = tid >> 4;

    float acc[8][8] = {};

    for (int kt = 0; kt < K; kt += BK) {
        // Load A/B tiles (BM x BK), transpose into smem as [BK][BM]
        #pragma unroll
        for (int i = 0; i < 2; ++i) {
            int f  = tid + i * 256;       // 0..511 float4 slots
            int r  = f >> 2;              // row within tile (0..127)
            int c4 = (f & 3) << 2;        // col offset (0,4,8,12)
            float4 va = *(const float4*)(A + (size_t)(bm + r) * lda + kt + c4);
            As[c4 + 0][r] = va.x; As[c4 + 1][r] = va.y;
            As[c4 + 2][r] = va.z; As[c4 + 3][r] = va.w;
            float4 vb = *(const float4*)(B + (size_t)(bn + r) * ldb + kt + c4);
            Bs[c4 + 0][r] = vb.x; Bs[c4 + 1][r] = vb.y;
            Bs[c4 + 2][r] = vb.z; Bs[c4 + 3][r] = vb.w;
        }
        __syncthreads();

        #pragma unroll
        for (int kk = 0; kk < BK; ++kk) {
            float4 a0 = *(const float4*)&As[kk][ty * 8];
            float4 a1 = *(const float4*)&As[kk][ty * 8 + 4];
            float4 b0 = *(const float4*)&Bs[kk][tx * 8];
            float4 b1 = *(const float4*)&Bs[kk][tx * 8 + 4];
            float ra[8] = {a0.x, a0.y, a0.z, a0.w, a1.x, a1.y, a1.z, a1.w};
            float rb[8] = {b0.x, b0.y, b0.z, b0.w, b1.x, b1.y, b1.z, b1.w};
            #pragma unroll
            for (int i = 0; i < 8; ++i)
                #pragma unroll
                for (int j = 0; j < 8; ++j)
                    acc[i][j] = fmaf(ra[i], rb[j], acc[i][j]);
        }
        __syncthreads();
    }

    #pragma unroll
    for (int i = 0; i < 8; ++i) {
        float* crow = C + (size_t)(bm + ty * 8 + i) * ldc + bn + tx * 8;
        *(float4*)(crow)     = make_float4(acc[i][0], acc[i][1], acc[i][2], acc[i][3]);
        *(float4*)(crow + 4) = make_float4(acc[i][4], acc[i][5], acc[i][6], acc[i][7]);
    }
}

// C[m,n] = sum_k A[k*lda + m] * B[k*ldb + n]   (both operands K-major, "TN")
__global__ __launch_bounds__(256) void gemm_tn(
    const float* __restrict__ A, const float* __restrict__ B, float* __restrict__ C,
    int K, int lda, int ldb, int ldc,
    size_t sA, size_t sB, size_t sC)
{
    A += (size_t)blockIdx.z * sA;
    B += (size_t)blockIdx.z * sB;
    C += (size_t)blockIdx.z * sC;

    __shared__ float As[BK][BM];
    __shared__ float Bs[BK][BN];

    const int bm  = blockIdx.y * BM;
    const int bn  = blockIdx.x * BN;
    const int tid = threadIdx.x;
    const int tx  = tid & 15;
    const int ty  = tid >> 4;

    float acc[8][8] = {};

    for (int kt = 0; kt < K; kt += BK) {
        // Tiles are already [BK][128] in global — direct vectorized copy
        #pragma unroll
        for (int i = 0; i < 2; ++i) {
            int f  = tid + i * 256;       // 0..511 float4 slots
            int r  = f >> 5;              // k-row within tile (0..15)
            int m4 = (f & 31) << 2;       // 0..124
            *(float4*)&As[r][m4] = *(const float4*)(A + (size_t)(kt + r) * lda + bm + m4);
            *(float4*)&Bs[r][m4] = *(const float4*)(B + (size_t)(kt + r) * ldb + bn + m4);
        }
        __syncthreads();

        #pragma unroll
        for (int kk = 0; kk < BK; ++kk) {
            float4 a0 = *(const float4*)&As[kk][ty * 8];
            float4 a1 = *(const float4*)&As[kk][ty * 8 + 4];
            float4 b0 = *(const float4*)&Bs[kk][tx * 8];
            float4 b1 = *(const float4*)&Bs[kk][tx * 8 + 4];
            float ra[8] = {a0.x, a0.y, a0.z, a0.w, a1.x, a1.y, a1.z, a1.w};
            float rb[8] = {b0.x, b0.y, b0.z, b0.w, b1.x, b1.y, b1.z, b1.w};
            #pragma unroll
            for (int i = 0; i < 8; ++i)
                #pragma unroll
                for (int j = 0; j < 8; ++j)
                    acc[i][j] = fmaf(ra[i], rb[j], acc[i][j]);
        }
        __syncthreads();
    }

    #pragma unroll
    for (int i = 0; i < 8; ++i) {
        float* crow = C + (size_t)(bm + ty * 8 + i) * ldc + bn + tx * 8;
        *(float4*)(crow)     = make_float4(acc[i][0], acc[i][1], acc[i][2], acc[i][3]);
        *(float4*)(crow + 4) = make_float4(acc[i][4], acc[i][5], acc[i][6], acc[i][7]);
    }
}

// Row-wise softmax over the last axis of P[n][k][:] (= softmax over q), then /DIM.
__global__ __launch_bounds__(256) void softmax_div(float* __restrict__ P)
{
    float* p = P + (size_t)blockIdx.x * SEQ;
    const int tid  = threadIdx.x;
    const int lane = tid & 31;
    const int wid  = tid >> 5;

    float v[8];
    float mx = -3.4e38f;
    #pragma unroll
    for (int i = 0; i < 8; ++i) {
        v[i] = p[tid + (i << 8)];
        mx = fmaxf(mx, v[i]);
    }
    #pragma unroll
    for (int o = 16; o > 0; o >>= 1)
        mx = fmaxf(mx, __shfl_xor_sync(0xffffffffu, mx, o));

    __shared__ float smax[8];
    __shared__ float ssum[8];
    if (lane == 0) smax[wid] = mx;
    __syncthreads();
    mx = smax[0];
    #pragma unroll
    for (int w = 1; w < 8; ++w) mx = fmaxf(mx, smax[w]);

    float s = 0.f;
    #pragma unroll
    for (int i = 0; i < 8; ++i) {
        v[i] = expf(v[i] - mx);
        s += v[i];
    }
    #pragma unroll
    for (int o = 16; o > 0; o >>= 1)
        s += __shfl_xor_sync(0xffffffffu, s, o);
    if (lane == 0) ssum[wid] = s;
    __syncthreads();
    s = ssum[0];
    #pragma unroll
    for (int w = 1; w < 8; ++w) s += ssum[w];

    const float inv = 1.0f / (s * (float)DIM);
    #pragma unroll
    for (int i = 0; i < 8; ++i)
        p[tid + (i << 8)] = v[i] * inv;
}

extern "C" void kernel_launch(void* const* d_in, const int* in_sizes, int n_in,
                              void* d_out, int out_size)
{
    const float* v  = (const float*)d_in[0];
    const float* k  = (const float*)d_in[1];
    const float* q  = (const float*)d_in[2];
    const float* WV = (const float*)d_in[3];
    const float* WQ = (const float*)d_in[4];
    const float* WK = (const float*)d_in[5];
    float* out = (float*)d_out;

    float *wv, *wq, *wk, *p;
    cudaGetSymbolAddress((void**)&wv, g_wv);
    cudaGetSymbolAddress((void**)&wq, g_wq);
    cudaGetSymbolAddress((void**)&wk, g_wk);
    cudaGetSymbolAddress((void**)&p,  g_p);

    const dim3 blk(256);

    // Projections: [NB*SEQ, DIM] = X @ W^T  (batch-independent)
    const dim3 gproj(DIM / BN, (NB * SEQ) / BM, 1);
    gemm_nt<<<gproj, blk>>>(v, WV, wv, DIM, DIM, DIM, DIM, 0, 0, 0);
    gemm_nt<<<gproj, blk>>>(q, WQ, wq, DIM, DIM, DIM, DIM, 0, 0, 0);
    gemm_nt<<<gproj, blk>>>(k, WK, wk, DIM, DIM, DIM, DIM, 0, 0, 0);

    // Scores, stored transposed: P[n][k][q] = wk[n,k,:] · wq[n,q,:]
    const dim3 gsc(SEQ / BN, SEQ / BM, NB);
    gemm_nt<<<gsc, blk>>>(wk, wq, p, DIM, DIM, DIM, SEQ,
                          (size_t)SEQ * DIM, (size_t)SEQ * DIM, (size_t)SEQ * SEQ);

    // Softmax over q (contiguous rows of P) + divide by DIM
    softmax_div<<<NB * SEQ, 256>>>(p);

    // out[n,q,o] = sum_k P[n][k][q] * wv[n][k][o]   (TN GEMM, both K-major)
    const dim3 gout(DIM / BN, SEQ / BM, NB);
    gemm_tn<<<gout, blk>>>(p, wv, out, SEQ, SEQ, DIM, DIM,
                           (size_t)SEQ * SEQ, (size_t)SEQ * DIM, (size_t)SEQ * DIM);
}